// round 6
// baseline (speedup 1.0000x reference)
#include <cuda_runtime.h>
#include <cstdint>

// AdaMoeLayer: out[t] = sum_e w[t,e]*(x[t] @ W_e + b_e),  T=32768, D=512, E=8.
// tf32 mma.sync. kt-outer/expert-inner stages with per-stage register fold
// (o += w_e * acc). 2 CTAs/SM for barrier overlap. Paired-k SMEM layouts so
// every fragment load is a single LDS.64.

#define D_DIM 512
#define E_DIM 8
#define T_TOK 32768
#define MAX_THRESHOLD 0.25f

// ---- static device scratch ----
__device__ float g_w[T_TOK * E_DIM];                      // gate weights, 1 MB
__device__ float g_Wt[(size_t)E_DIM * D_DIM * D_DIM];     // tf32 W', [e][n][k-perm], 8 MB
__device__ float g_Xt[(size_t)T_TOK * D_DIM];             // tf32 X,  [t][k-perm], 64 MB

// ---------------------------------------------------------------------------
__device__ __forceinline__ uint32_t smem_u32(const void* p) {
    uint32_t a;
    asm("{ .reg .u64 t; cvta.to.shared.u64 t, %1; cvt.u32.u64 %0, t; }"
        : "=r"(a) : "l"(p));
    return a;
}
__device__ __forceinline__ void cp16(uint32_t dst, const void* src) {
    asm volatile("cp.async.cg.shared.global [%0], [%1], 16;\n"
                 :: "r"(dst), "l"(__cvta_generic_to_global(src)) : "memory");
}
__device__ __forceinline__ uint32_t cvt_tf32(float x) {
    uint32_t u;
    asm("cvt.rna.tf32.f32 %0, %1;" : "=r"(u) : "f"(x));
    return u;
}
__device__ __forceinline__ void mma_tf32(float* c, const uint32_t* a, const uint32_t* b) {
    asm volatile(
        "mma.sync.aligned.m16n8k8.row.col.f32.tf32.tf32.f32 "
        "{%0,%1,%2,%3}, {%4,%5,%6,%7}, {%8,%9}, {%0,%1,%2,%3};"
        : "+f"(c[0]), "+f"(c[1]), "+f"(c[2]), "+f"(c[3])
        : "r"(a[0]), "r"(a[1]), "r"(a[2]), "r"(a[3]), "r"(b[0]), "r"(b[1]));
}

// ---------------------------------------------------------------------------
// Kernel 1: gating. One warp per token.
// ---------------------------------------------------------------------------
__global__ __launch_bounds__(256) void gating_kernel(
    const float* __restrict__ x,
    const float* __restrict__ Wg, const float* __restrict__ bg,
    const float* __restrict__ Wt, const float* __restrict__ bt)
{
    __shared__ float sWg[E_DIM][D_DIM];
    __shared__ float sWt[D_DIM];
    const int tid = threadIdx.x;
    for (int i = tid; i < E_DIM * D_DIM; i += 256) {
        int e = i / D_DIM, d = i - e * D_DIM;
        sWg[e][d] = Wg[d * E_DIM + e];
    }
    for (int i = tid; i < D_DIM; i += 256) sWt[i] = Wt[i];
    __syncthreads();

    const int warp = tid >> 5, lane = tid & 31;
    const int t = blockIdx.x * 8 + warp;
    const float* xr = x + (size_t)t * D_DIM;

    float acc[9];
#pragma unroll
    for (int e = 0; e < 9; e++) acc[e] = 0.f;
#pragma unroll
    for (int i = 0; i < D_DIM / 32; i++) {
        int d = lane + 32 * i;
        float xv = xr[d];
#pragma unroll
        for (int e = 0; e < E_DIM; e++) acc[e] = fmaf(xv, sWg[e][d], acc[e]);
        acc[8] = fmaf(xv, sWt[d], acc[8]);
    }
#pragma unroll
    for (int off = 16; off > 0; off >>= 1)
#pragma unroll
        for (int e = 0; e < 9; e++) acc[e] += __shfl_xor_sync(0xffffffffu, acc[e], off);

    float logit[E_DIM];
#pragma unroll
    for (int e = 0; e < E_DIM; e++) logit[e] = acc[e] + bg[e];
    float m = logit[0];
#pragma unroll
    for (int e = 1; e < E_DIM; e++) m = fmaxf(m, logit[e]);
    float p[E_DIM], s = 0.f;
#pragma unroll
    for (int e = 0; e < E_DIM; e++) { p[e] = expf(logit[e] - m); s += p[e]; }
    float inv_s = 1.f / s;
    float thr = (1.f / (1.f + expf(-(acc[8] + bt[0])))) * MAX_THRESHOLD;

    float w[E_DIM], ws = 0.f;
#pragma unroll
    for (int e = 0; e < E_DIM; e++) {
        float a = p[e] * inv_s - thr;
        w[e] = (a >= 0.f) ? a : 0.f;
        ws += w[e];
    }
    if (ws == 0.f) ws = 1.f;
    float inv_ws = 1.f / ws;

    if (lane < E_DIM) {
        float v = 0.f;
#pragma unroll
        for (int e = 0; e < E_DIM; e++) if (lane == e) v = w[e];
        g_w[t * E_DIM + lane] = v * inv_ws;
    }
}

// ---------------------------------------------------------------------------
// Kernel 2a: X -> tf32, paired-k layout. Each thread handles one 8-k group:
// out order [k0, k0+4, k0+1, k0+5, k0+2, k0+6, k0+3, k0+7].
// ---------------------------------------------------------------------------
__global__ __launch_bounds__(256) void xprep_kernel(const float* __restrict__ X)
{
    size_t gidx = (size_t)blockIdx.x * 256 + threadIdx.x;   // 8-float group
    size_t base = gidx * 8;
    float4 f0 = *reinterpret_cast<const float4*>(X + base);
    float4 f1 = *reinterpret_cast<const float4*>(X + base + 4);
    uint4 o0, o1;
    o0.x = cvt_tf32(f0.x); o0.y = cvt_tf32(f1.x);   // k0, k4
    o0.z = cvt_tf32(f0.y); o0.w = cvt_tf32(f1.y);   // k1, k5
    o1.x = cvt_tf32(f0.z); o1.y = cvt_tf32(f1.z);   // k2, k6
    o1.z = cvt_tf32(f0.w); o1.w = cvt_tf32(f1.w);   // k3, k7
    *reinterpret_cast<uint4*>(g_Xt + base)     = o0;
    *reinterpret_cast<uint4*>(g_Xt + base + 4) = o1;
}

// ---------------------------------------------------------------------------
// Kernel 2b: W[e][k][n] -> W'[e][n][k-perm], tf32.
// ---------------------------------------------------------------------------
__global__ void wprep_kernel(const float* __restrict__ W)
{
    __shared__ float tile[32][33];
    int e = blockIdx.z;
    int nb = blockIdx.x * 32, kb = blockIdx.y * 32;
    int tx = threadIdx.x, ty = threadIdx.y;   // 32 x 8
    const float* Ws = W + (size_t)e * D_DIM * D_DIM;
#pragma unroll
    for (int j = 0; j < 32; j += 8)
        tile[ty + j][tx] = Ws[(size_t)(kb + ty + j) * D_DIM + nb + tx];
    __syncthreads();
    // permuted k position within each 8-group
    int grp = tx >> 3, j8 = tx & 7;
    int p = (j8 < 4) ? (2 * j8) : (2 * (j8 - 4) + 1);
    int pk = kb + grp * 8 + p;
#pragma unroll
    for (int j = 0; j < 32; j += 8) {
        float v = tile[tx][ty + j];
        g_Wt[((size_t)e * D_DIM + nb + ty + j) * D_DIM + pk] =
            __uint_as_float(cvt_tf32(v));
    }
}

// ---------------------------------------------------------------------------
// Kernel 3: main GEMM. Grid (8 N-tiles, 256 M-tiles), 256 threads, 2 CTAs/SM.
// CTA tile 128x64; 8 warps (4Mx2N); warp tile 32x32.
// Stages: 16 kt x 8 experts = 128; X loaded once per kt (double-buffered),
// B 3-deep ring. Per-stage fold: o += w[e] * acc, acc reset.
// ---------------------------------------------------------------------------
#define KC 32
#define ROW_STRIDE 40                        // floats, ==8 mod 32: LDS.64 clean
#define XB_WORDS (128 * ROW_STRIDE)          // 5120
#define BB_WORDS (64 * ROW_STRIDE)           // 2560
#define SW_OFF 0                             // [e][m] 8*128 = 1024
#define BIAS_OFF 1024                        // [e][n] 8*64  = 512
#define X_OFF 1536                           // 2 buffers
#define B_OFF (X_OFF + 2 * XB_WORDS)         // 11776; 3 buffers
#define SMEM_WORDS (B_OFF + 3 * BB_WORDS)    // 19456
#define SMEM_BYTES (SMEM_WORDS * 4)          // 77824

__device__ __forceinline__ void issue_stage(
    int tid, uint32_t sm_base, int s, int t0, int n0)
{
    const int kt = s >> 3, e = s & 7, bbuf = s % 3;
    // B chunk: 64 n-rows x 8 16B chunks (512 total, 2/thread)
#pragma unroll
    for (int i = 0; i < 2; i++) {
        int id = tid + (i << 8);
        int row = id >> 3, ch = id & 7;
        uint32_t dst = sm_base + (B_OFF + bbuf * BB_WORDS + row * ROW_STRIDE + ch * 4) * 4;
        cp16(dst, g_Wt + ((size_t)e * D_DIM + n0 + row) * D_DIM + kt * KC + ch * 4);
    }
    // X chunk: only on expert-0 stages (1024 chunks, 4/thread)
    if (e == 0) {
        const int xbuf = kt & 1;
#pragma unroll
        for (int i = 0; i < 4; i++) {
            int id = tid + (i << 8);
            int row = id >> 3, ch = id & 7;
            uint32_t dst = sm_base + (X_OFF + xbuf * XB_WORDS + row * ROW_STRIDE + ch * 4) * 4;
            cp16(dst, g_Xt + (size_t)(t0 + row) * D_DIM + kt * KC + ch * 4);
        }
    }
    asm volatile("cp.async.commit_group;\n" ::: "memory");
}

__global__ __launch_bounds__(256, 2) void moe_mma_kernel(
    const float* __restrict__ bexp,
    float* __restrict__ out)
{
    extern __shared__ float smem[];
    const uint32_t sm_base = smem_u32(smem);
    const int tid = threadIdx.x;
    const int lane = tid & 31, wid = tid >> 5;
    const int g = lane >> 2, t4 = lane & 3;
    const int wm = (wid >> 1) * 32, wn = (wid & 1) * 32;
    const int n0 = blockIdx.x * 64;
    const int t0 = blockIdx.y * 128;

    // stage gate weights [e][m] and bias [e][n]
    for (int i = tid; i < 128 * E_DIM; i += 256) {
        int m = i >> 3, e = i & 7;
        smem[SW_OFF + e * 128 + m] = g_w[(size_t)(t0 + m) * E_DIM + e];
    }
    for (int i = tid; i < E_DIM * 64; i += 256) {
        int e = i >> 6, c = i & 63;
        smem[BIAS_OFF + i] = bexp[e * D_DIM + n0 + c];
    }

    float acc[2][4][4], o[2][4][4];
#pragma unroll
    for (int mt = 0; mt < 2; mt++)
#pragma unroll
        for (int nt = 0; nt < 4; nt++)
#pragma unroll
            for (int j = 0; j < 4; j++) { acc[mt][nt][j] = 0.f; o[mt][nt][j] = 0.f; }

    issue_stage(tid, sm_base, 0, t0, n0);
    issue_stage(tid, sm_base, 1, t0, n0);

#pragma unroll 1
    for (int s = 0; s < 128; ++s) {
        if (s < 127) asm volatile("cp.async.wait_group 1;\n" ::: "memory");
        else         asm volatile("cp.async.wait_group 0;\n" ::: "memory");
        __syncthreads();
        if (s + 2 < 128) issue_stage(tid, sm_base, s + 2, t0, n0);

        const int kt = s >> 3, e = s & 7;
        const float* Xb = smem + X_OFF + (kt & 1) * XB_WORDS;
        const float* Bb = smem + B_OFF + (s % 3) * BB_WORDS;

#pragma unroll
        for (int j8 = 0; j8 < 4; j8++) {       // 4 k8-groups in the 32-chunk
            uint32_t a[2][4];
#pragma unroll
            for (int mt = 0; mt < 2; mt++) {
                int r = wm + mt * 16 + g;
                uint2 p0 = *reinterpret_cast<const uint2*>(
                    Xb + r * ROW_STRIDE + j8 * 8 + t4 * 2);
                uint2 p1 = *reinterpret_cast<const uint2*>(
                    Xb + (r + 8) * ROW_STRIDE + j8 * 8 + t4 * 2);
                a[mt][0] = p0.x; a[mt][2] = p0.y;
                a[mt][1] = p1.x; a[mt][3] = p1.y;
            }
#pragma unroll
            for (int nt = 0; nt < 4; nt++) {
                int n = wn + nt * 8 + g;
                uint2 bp = *reinterpret_cast<const uint2*>(
                    Bb + n * ROW_STRIDE + j8 * 8 + t4 * 2);
                uint32_t b[2] = {bp.x, bp.y};
                mma_tf32(acc[0][nt], a[0], b);
                mma_tf32(acc[1][nt], a[1], b);
            }
        }

        // fold this expert's partial into o, reset acc
#pragma unroll
        for (int mt = 0; mt < 2; mt++) {
#pragma unroll
            for (int rr = 0; rr < 2; rr++) {
                float wv = smem[SW_OFF + e * 128 + wm + mt * 16 + g + rr * 8];
#pragma unroll
                for (int nt = 0; nt < 4; nt++) {
#pragma unroll
                    for (int j = 0; j < 2; j++) {
                        o[mt][nt][rr * 2 + j] =
                            fmaf(wv, acc[mt][nt][rr * 2 + j], o[mt][nt][rr * 2 + j]);
                        acc[mt][nt][rr * 2 + j] = 0.f;
                    }
                }
            }
        }
    }

    __syncthreads();

    // ---- epilogue: add sum_e w_te * b_e[n], write out ----
#pragma unroll
    for (int mt = 0; mt < 2; mt++) {
#pragma unroll
        for (int rr = 0; rr < 2; rr++) {
            int row = wm + mt * 16 + g + rr * 8;
            float wv[E_DIM];
#pragma unroll
            for (int e = 0; e < E_DIM; e++) wv[e] = smem[SW_OFF + e * 128 + row];
#pragma unroll
            for (int nt = 0; nt < 4; nt++) {
                int cl = wn + nt * 8 + 2 * t4;
                float b0 = 0.f, b1 = 0.f;
#pragma unroll
                for (int e = 0; e < E_DIM; e++) {
                    b0 = fmaf(wv[e], smem[BIAS_OFF + e * 64 + cl], b0);
                    b1 = fmaf(wv[e], smem[BIAS_OFF + e * 64 + cl + 1], b1);
                }
                float2 v;
                v.x = o[mt][nt][rr * 2 + 0] + b0;
                v.y = o[mt][nt][rr * 2 + 1] + b1;
                *reinterpret_cast<float2*>(out + (size_t)(t0 + row) * D_DIM + n0 + cl) = v;
            }
        }
    }
}

// ---------------------------------------------------------------------------
extern "C" void kernel_launch(void* const* d_in, const int* in_sizes, int n_in,
                              void* d_out, int out_size)
{
    const float* x    = (const float*)d_in[0];
    const float* Wg   = (const float*)d_in[1];
    const float* bg   = (const float*)d_in[2];
    const float* Wt   = (const float*)d_in[3];
    const float* bt   = (const float*)d_in[4];
    const float* Wexp = (const float*)d_in[5];
    const float* bexp = (const float*)d_in[6];
    float* out        = (float*)d_out;

    const int T = in_sizes[0] / D_DIM;          // 32768

    cudaFuncSetAttribute(moe_mma_kernel,
                         cudaFuncAttributeMaxDynamicSharedMemorySize, SMEM_BYTES);

    gating_kernel<<<T / 8, 256>>>(x, Wg, bg, Wt, bt);
    xprep_kernel<<<T * D_DIM / 8 / 256, 256>>>(x);
    wprep_kernel<<<dim3(16, 16, 8), dim3(32, 8)>>>(Wexp);
    moe_mma_kernel<<<dim3(8, T / 128), 256, SMEM_BYTES>>>(bexp, out);
}

// round 7
// speedup vs baseline: 1.1270x; 1.1270x over previous
#include <cuda_runtime.h>
#include <cuda_fp16.h>
#include <cstdint>

// AdaMoeLayer: out[t] = sum_e w[t,e]*(x[t] @ W_e + b_e),  T=32768, D=512, E=8.
// fp16 mma.sync m16n8k16, X split hi/lo (2 products), W rounded to fp16 once.
// kt-outer/expert-inner stages, per-stage register fold o += w_e * acc.

#define D_DIM 512
#define E_DIM 8
#define T_TOK 32768
#define MAX_THRESHOLD 0.25f

// ---- static device scratch ----
__device__ float g_w[T_TOK * E_DIM];                       // gate weights, 1 MB
__device__ __half g_Wh[(size_t)E_DIM * D_DIM * D_DIM];     // fp16 W' [e][n][k-perm], 4 MB
__device__ __half g_Xh[(size_t)T_TOK * D_DIM];             // fp16 X hi [t][k-perm], 32 MB
__device__ __half g_Xl[(size_t)T_TOK * D_DIM];             // fp16 X lo [t][k-perm], 32 MB

// ---------------------------------------------------------------------------
__device__ __forceinline__ uint32_t smem_u32(const void* p) {
    uint32_t a;
    asm("{ .reg .u64 t; cvta.to.shared.u64 t, %1; cvt.u32.u64 %0, t; }"
        : "=r"(a) : "l"(p));
    return a;
}
__device__ __forceinline__ void cp16(uint32_t dst, const void* src) {
    asm volatile("cp.async.cg.shared.global [%0], [%1], 16;\n"
                 :: "r"(dst), "l"(__cvta_generic_to_global(src)) : "memory");
}
__device__ __forceinline__ void mma_f16(float* c,
    uint32_t a0, uint32_t a1, uint32_t a2, uint32_t a3,
    uint32_t b0, uint32_t b1)
{
    asm volatile(
        "mma.sync.aligned.m16n8k16.row.col.f32.f16.f16.f32 "
        "{%0,%1,%2,%3}, {%4,%5,%6,%7}, {%8,%9}, {%0,%1,%2,%3};"
        : "+f"(c[0]), "+f"(c[1]), "+f"(c[2]), "+f"(c[3])
        : "r"(a0), "r"(a1), "r"(a2), "r"(a3), "r"(b0), "r"(b1));
}

// ---------------------------------------------------------------------------
// Kernel 1: gating. One warp per token.
// ---------------------------------------------------------------------------
__global__ __launch_bounds__(256) void gating_kernel(
    const float* __restrict__ x,
    const float* __restrict__ Wg, const float* __restrict__ bg,
    const float* __restrict__ Wt, const float* __restrict__ bt)
{
    __shared__ float sWg[E_DIM][D_DIM];
    __shared__ float sWt[D_DIM];
    const int tid = threadIdx.x;
    for (int i = tid; i < E_DIM * D_DIM; i += 256) {
        int e = i / D_DIM, d = i - e * D_DIM;
        sWg[e][d] = Wg[d * E_DIM + e];
    }
    for (int i = tid; i < D_DIM; i += 256) sWt[i] = Wt[i];
    __syncthreads();

    const int warp = tid >> 5, lane = tid & 31;
    const int t = blockIdx.x * 8 + warp;
    const float* xr = x + (size_t)t * D_DIM;

    float acc[9];
#pragma unroll
    for (int e = 0; e < 9; e++) acc[e] = 0.f;
#pragma unroll
    for (int i = 0; i < D_DIM / 32; i++) {
        int d = lane + 32 * i;
        float xv = xr[d];
#pragma unroll
        for (int e = 0; e < E_DIM; e++) acc[e] = fmaf(xv, sWg[e][d], acc[e]);
        acc[8] = fmaf(xv, sWt[d], acc[8]);
    }
#pragma unroll
    for (int off = 16; off > 0; off >>= 1)
#pragma unroll
        for (int e = 0; e < 9; e++) acc[e] += __shfl_xor_sync(0xffffffffu, acc[e], off);

    float logit[E_DIM];
#pragma unroll
    for (int e = 0; e < E_DIM; e++) logit[e] = acc[e] + bg[e];
    float m = logit[0];
#pragma unroll
    for (int e = 1; e < E_DIM; e++) m = fmaxf(m, logit[e]);
    float p[E_DIM], s = 0.f;
#pragma unroll
    for (int e = 0; e < E_DIM; e++) { p[e] = expf(logit[e] - m); s += p[e]; }
    float inv_s = 1.f / s;
    float thr = (1.f / (1.f + expf(-(acc[8] + bt[0])))) * MAX_THRESHOLD;

    float w[E_DIM], ws = 0.f;
#pragma unroll
    for (int e = 0; e < E_DIM; e++) {
        float a = p[e] * inv_s - thr;
        w[e] = (a >= 0.f) ? a : 0.f;
        ws += w[e];
    }
    if (ws == 0.f) ws = 1.f;
    float inv_ws = 1.f / ws;

    if (lane < E_DIM) {
        float v = 0.f;
#pragma unroll
        for (int e = 0; e < E_DIM; e++) if (lane == e) v = w[e];
        g_w[t * E_DIM + lane] = v * inv_ws;
    }
}

// ---------------------------------------------------------------------------
// Kernel 2a: X -> fp16 hi/lo, pair-permuted within each 16-k group.
// Pair p (0..7) stored at u32 slot s(p) = p<4 ? 2p : 2(p-4)+1.
// One thread per 16-k group.
// ---------------------------------------------------------------------------
__global__ __launch_bounds__(256) void xprep_kernel(const float* __restrict__ X)
{
    size_t idx = (size_t)blockIdx.x * 256 + threadIdx.x;   // group index
    size_t base = idx * 16;
    float v[16];
#pragma unroll
    for (int i = 0; i < 4; i++)
        *reinterpret_cast<float4*>(v + i * 4) =
            *reinterpret_cast<const float4*>(X + base + i * 4);

    uint32_t oh[8], ol[8];
#pragma unroll
    for (int p = 0; p < 8; p++) {
        float v0 = v[2 * p], v1 = v[2 * p + 1];
        __half h0 = __float2half(v0), h1 = __float2half(v1);
        __half l0 = __float2half(v0 - __half2float(h0));
        __half l1 = __float2half(v1 - __half2float(h1));
        int s = (p < 4) ? 2 * p : 2 * (p - 4) + 1;
        __half2 ph; ph.x = h0; ph.y = h1;
        __half2 pl; pl.x = l0; pl.y = l1;
        oh[s] = *reinterpret_cast<uint32_t*>(&ph);
        ol[s] = *reinterpret_cast<uint32_t*>(&pl);
    }
    uint4* dh = reinterpret_cast<uint4*>(g_Xh + base);
    uint4* dl = reinterpret_cast<uint4*>(g_Xl + base);
    dh[0] = make_uint4(oh[0], oh[1], oh[2], oh[3]);
    dh[1] = make_uint4(oh[4], oh[5], oh[6], oh[7]);
    dl[0] = make_uint4(ol[0], ol[1], ol[2], ol[3]);
    dl[1] = make_uint4(ol[4], ol[5], ol[6], ol[7]);
}

// ---------------------------------------------------------------------------
// Kernel 2b: W[e][k][n] -> fp16 W'[e][n][k-perm].
// ---------------------------------------------------------------------------
__global__ void wprep_kernel(const float* __restrict__ W)
{
    __shared__ float tile[32][33];
    int e = blockIdx.z;
    int nb = blockIdx.x * 32, kb = blockIdx.y * 32;
    int tx = threadIdx.x, ty = threadIdx.y;   // 32 x 8
    const float* Ws = W + (size_t)e * D_DIM * D_DIM;
#pragma unroll
    for (int j = 0; j < 32; j += 8)
        tile[ty + j][tx] = Ws[(size_t)(kb + ty + j) * D_DIM + nb + tx];
    __syncthreads();
    // permuted k position
    int grp = tx >> 4, p = (tx & 15) >> 1, lo = tx & 1;
    int s = (p < 4) ? 2 * p : 2 * (p - 4) + 1;
    int kp = kb + grp * 16 + s * 2 + lo;
#pragma unroll
    for (int j = 0; j < 32; j += 8)
        g_Wh[((size_t)e * D_DIM + nb + ty + j) * D_DIM + kp] =
            __float2half(tile[tx][ty + j]);
}

// ---------------------------------------------------------------------------
// Kernel 3: main GEMM. Grid (8 N-tiles, 256 M-tiles), 256 threads, 2 CTAs/SM.
// CTA tile 128x64; 8 warps, each owning a 16x64 strip (1 m16 x 8 n8).
// Stages: 16 kt x 8 experts = 128; X loaded once per kt; per-stage fold.
// ---------------------------------------------------------------------------
#define RS 24                                // u32 per row (96 B, LDS.64 clean)
#define XB_U32 (128 * RS)                    // 3072
#define BB_U32 (64 * RS)                     // 1536
#define SW_OFF 0                             // [e][m] fp32, 1024 u32
#define BIAS_OFF 1024                        // [e][n] fp32, 512 u32
#define XH_OFF 1536                          // 2 buffers
#define XL_OFF (XH_OFF + 2 * XB_U32)         // 7680
#define B_OFF  (XL_OFF + 2 * XB_U32)         // 13824; 3 buffers
#define SMEM_U32 (B_OFF + 3 * BB_U32)        // 18432
#define SMEM_BYTES (SMEM_U32 * 4)            // 73728

__device__ __forceinline__ void issue_stage(
    int tid, uint32_t sm_base, int s, int t0, int n0)
{
    const int kt = s >> 3, e = s & 7, bbuf = s % 3;
    // B chunk: 64 n-rows x 4 16B chunks (256 cp16, 1/thread)
    {
        int row = tid >> 2, ch = tid & 3;
        uint32_t dst = sm_base + (B_OFF + bbuf * BB_U32 + row * RS + ch * 4) * 4;
        cp16(dst, g_Wh + ((size_t)e * D_DIM + n0 + row) * D_DIM + kt * 32 + ch * 8);
    }
    // X chunks on expert-0 stages: hi+lo, 512 cp16 each (2/thread each)
    if (e == 0) {
        const int xbuf = kt & 1;
#pragma unroll
        for (int i = 0; i < 2; i++) {
            int id = tid + (i << 8);
            int row = id >> 2, ch = id & 3;
            uint32_t dh = sm_base + (XH_OFF + xbuf * XB_U32 + row * RS + ch * 4) * 4;
            uint32_t dl = sm_base + (XL_OFF + xbuf * XB_U32 + row * RS + ch * 4) * 4;
            const size_t src = (size_t)(t0 + row) * D_DIM + kt * 32 + ch * 8;
            cp16(dh, g_Xh + src);
            cp16(dl, g_Xl + src);
        }
    }
    asm volatile("cp.async.commit_group;\n" ::: "memory");
}

__global__ __launch_bounds__(256, 2) void moe_mma_kernel(
    const float* __restrict__ bexp,
    float* __restrict__ out)
{
    extern __shared__ float smem[];
    uint32_t* smemU = reinterpret_cast<uint32_t*>(smem);
    const uint32_t sm_base = smem_u32(smem);
    const int tid = threadIdx.x;
    const int lane = tid & 31, wid = tid >> 5;
    const int g = lane >> 2, t4 = lane & 3;
    const int n0 = blockIdx.x * 64;
    const int t0 = blockIdx.y * 128;
    const int r0 = wid * 16 + g;               // this thread's A row (and +8)

    // stage gate weights [e][m] and bias [e][n]
    for (int i = tid; i < 128 * E_DIM; i += 256) {
        int m = i >> 3, e = i & 7;
        smem[SW_OFF + e * 128 + m] = g_w[(size_t)(t0 + m) * E_DIM + e];
    }
    for (int i = tid; i < E_DIM * 64; i += 256) {
        int e = i >> 6, c = i & 63;
        smem[BIAS_OFF + i] = bexp[e * D_DIM + n0 + c];
    }

    float o[8][4];
#pragma unroll
    for (int nt = 0; nt < 8; nt++)
#pragma unroll
        for (int j = 0; j < 4; j++) o[nt][j] = 0.f;

    issue_stage(tid, sm_base, 0, t0, n0);
    issue_stage(tid, sm_base, 1, t0, n0);

#pragma unroll 1
    for (int s = 0; s < 128; ++s) {
        if (s < 127) asm volatile("cp.async.wait_group 1;\n" ::: "memory");
        else         asm volatile("cp.async.wait_group 0;\n" ::: "memory");
        __syncthreads();
        if (s + 2 < 128) issue_stage(tid, sm_base, s + 2, t0, n0);

        const int kt = s >> 3, e = s & 7;
        const uint32_t* Xh = smemU + XH_OFF + (kt & 1) * XB_U32;
        const uint32_t* Xl = smemU + XL_OFF + (kt & 1) * XB_U32;
        const uint32_t* Bb = smemU + B_OFF + (s % 3) * BB_U32;

        float acc[8][4];
#pragma unroll
        for (int nt = 0; nt < 8; nt++)
#pragma unroll
            for (int j = 0; j < 4; j++) acc[nt][j] = 0.f;

#pragma unroll
        for (int j = 0; j < 2; j++) {          // two k16 groups in the 32-chunk
            uint2 ah0 = *reinterpret_cast<const uint2*>(Xh + r0 * RS + j * 8 + t4 * 2);
            uint2 ah1 = *reinterpret_cast<const uint2*>(Xh + (r0 + 8) * RS + j * 8 + t4 * 2);
            uint2 al0 = *reinterpret_cast<const uint2*>(Xl + r0 * RS + j * 8 + t4 * 2);
            uint2 al1 = *reinterpret_cast<const uint2*>(Xl + (r0 + 8) * RS + j * 8 + t4 * 2);
#pragma unroll
            for (int nt = 0; nt < 8; nt++) {
                uint2 b = *reinterpret_cast<const uint2*>(
                    Bb + (nt * 8 + g) * RS + j * 8 + t4 * 2);
                mma_f16(acc[nt], ah0.x, ah1.x, ah0.y, ah1.y, b.x, b.y);
                mma_f16(acc[nt], al0.x, al1.x, al0.y, al1.y, b.x, b.y);
            }
        }

        // fold this expert's partial into o
#pragma unroll
        for (int rr = 0; rr < 2; rr++) {
            float wv = smem[SW_OFF + e * 128 + wid * 16 + g + rr * 8];
#pragma unroll
            for (int nt = 0; nt < 8; nt++) {
                o[nt][rr * 2 + 0] = fmaf(wv, acc[nt][rr * 2 + 0], o[nt][rr * 2 + 0]);
                o[nt][rr * 2 + 1] = fmaf(wv, acc[nt][rr * 2 + 1], o[nt][rr * 2 + 1]);
            }
        }
    }

    __syncthreads();

    // ---- epilogue: add sum_e w_te * b_e[n], write out ----
#pragma unroll
    for (int rr = 0; rr < 2; rr++) {
        int row = wid * 16 + g + rr * 8;
        float wv[E_DIM];
#pragma unroll
        for (int e = 0; e < E_DIM; e++) wv[e] = smem[SW_OFF + e * 128 + row];
#pragma unroll
        for (int nt = 0; nt < 8; nt++) {
            int cl = nt * 8 + 2 * t4;
            float b0 = 0.f, b1 = 0.f;
#pragma unroll
            for (int e = 0; e < E_DIM; e++) {
                b0 = fmaf(wv[e], smem[BIAS_OFF + e * 64 + cl], b0);
                b1 = fmaf(wv[e], smem[BIAS_OFF + e * 64 + cl + 1], b1);
            }
            float2 v;
            v.x = o[nt][rr * 2 + 0] + b0;
            v.y = o[nt][rr * 2 + 1] + b1;
            *reinterpret_cast<float2*>(out + (size_t)(t0 + row) * D_DIM + n0 + cl) = v;
        }
    }
}

// ---------------------------------------------------------------------------
extern "C" void kernel_launch(void* const* d_in, const int* in_sizes, int n_in,
                              void* d_out, int out_size)
{
    const float* x    = (const float*)d_in[0];
    const float* Wg   = (const float*)d_in[1];
    const float* bg   = (const float*)d_in[2];
    const float* Wt   = (const float*)d_in[3];
    const float* bt   = (const float*)d_in[4];
    const float* Wexp = (const float*)d_in[5];
    const float* bexp = (const float*)d_in[6];
    float* out        = (float*)d_out;

    const int T = in_sizes[0] / D_DIM;          // 32768

    cudaFuncSetAttribute(moe_mma_kernel,
                         cudaFuncAttributeMaxDynamicSharedMemorySize, SMEM_BYTES);

    gating_kernel<<<T / 8, 256>>>(x, Wg, bg, Wt, bt);
    xprep_kernel<<<T * D_DIM / 16 / 256, 256>>>(x);
    wprep_kernel<<<dim3(16, 16, 8), dim3(32, 8)>>>(Wexp);
    moe_mma_kernel<<<dim3(8, T / 128), 256, SMEM_BYTES>>>(bexp, out);
}